// round 4
// baseline (speedup 1.0000x reference)
#include <cuda_runtime.h>

// Shapes fixed by the problem: L=1024, D=640, K=32, M=64
#define LMAX 1024
#define MM   64
#define KE   34    // e_scalar length (etype, pij, 32 rbf)

typedef unsigned long long u64;

// scratch: node projection + bias, 1024 x 64 fp32 = 256 KB (L2-resident)
__device__ float g_nb[LMAX * MM];

// ---- packed fp32x2 helpers (sm_103a dual-fp32 path) -----------------------
__device__ __forceinline__ u64 pack2(float lo, float hi) {
    u64 r; asm("mov.b64 %0, {%1, %2};" : "=l"(r) : "f"(lo), "f"(hi)); return r;
}
__device__ __forceinline__ u64 ffma2(u64 a, u64 b, u64 c) {
    u64 d; asm("fma.rn.f32x2 %0, %1, %2, %3;" : "=l"(d) : "l"(a), "l"(b), "l"(c));
    return d;
}
__device__ __forceinline__ float2 unpack2(u64 v) {
    unsigned lo, hi; asm("mov.b64 {%0, %1}, %2;" : "=r"(lo), "=r"(hi) : "l"(v));
    float2 f; f.x = __uint_as_float(lo); f.y = __uint_as_float(hi); return f;
}

// ---------------------------------------------------------------------------
// Kernel 1: nb[j,m] = sum_d S[j,d] * W_node[d,m] + b_edge[m]
// 128 blocks x 8 rows, 256 threads, register double-buffered staging
// ---------------------------------------------------------------------------
__global__ void __launch_bounds__(256) node_proj_kernel(
    const float* __restrict__ S,
    const float* __restrict__ W_node,
    const float* __restrict__ b_edge,
    int L, int D)
{
    const int m  = threadIdx.x & 63;
    const int jr = threadIdx.x >> 6;     // 0..3
    const int j0 = blockIdx.x * 8;

    __shared__ float sS[8][64];
    __shared__ float sW[64][65];

    float a0 = 0.f, a1 = 0.f;
    float wreg[16], s0, s1;

    // prefetch tile 0
    s0 = S[(size_t)(j0 + jr) * D + m];
    s1 = S[(size_t)(j0 + jr + 4) * D + m];
    #pragma unroll
    for (int r = 0; r < 16; r++)
        wreg[r] = W_node[(size_t)(r * 4 + jr) * MM + m];

    for (int d0 = 0; d0 < D; d0 += 64) {
        sS[jr][m]     = s0;
        sS[jr + 4][m] = s1;
        #pragma unroll
        for (int r = 0; r < 16; r++)
            sW[r * 4 + jr][m] = wreg[r];
        __syncthreads();
        int dn = d0 + 64;
        if (dn < D) {
            s0 = S[(size_t)(j0 + jr) * D + dn + m];
            s1 = S[(size_t)(j0 + jr + 4) * D + dn + m];
            #pragma unroll
            for (int r = 0; r < 16; r++)
                wreg[r] = W_node[(size_t)(dn + r * 4 + jr) * MM + m];
        }
        #pragma unroll
        for (int d = 0; d < 64; d++) {
            float w = sW[d][m];
            a0 = fmaf(sS[jr][d], w, a0);
            a1 = fmaf(sS[jr + 4][d], w, a1);
        }
        __syncthreads();
    }
    float b = b_edge[m];
    g_nb[(j0 + jr) * MM + m]     = a0 + b;
    g_nb[(j0 + jr + 4) * MM + m] = a1 + b;
}

// ---------------------------------------------------------------------------
// Kernel 2: one row per block (grid L, 128 threads). Lane-pair per edge:
// parity p owns interleaved m-set {8g+4p .. 8g+4p+3}, acc = 16 packed f32x2.
// No intra-chunk barriers, no smem round trip for u.
// ---------------------------------------------------------------------------
__global__ void __launch_bounds__(128, 5) edge_kernel(
    const float* __restrict__ P,
    const float* __restrict__ xyz,
    const float* __restrict__ rbf_mu,
    const float* __restrict__ rbf_sigma,
    const float* __restrict__ W_edge,
    const float* __restrict__ w_out,
    float* __restrict__ out,
    int L)
{
    __shared__ __align__(16) float sW[KE * MM];    // 8704 B, [k][m]
    __shared__ __align__(16) float sWo[MM];
    __shared__ float sMu[32], sI2[32];
    __shared__ int   sList[LMAX];
    __shared__ float sPij[LMAX];
    __shared__ float sDx[LMAX], sDy[LMAX], sDz[LMAX], sD[LMAX];
    __shared__ int   wsum[4];
    __shared__ float sred[4][3];

    const int tid  = threadIdx.x;
    const int lane = tid & 31;
    const int wrp  = tid >> 5;
    const int i    = blockIdx.x;

    for (int t = tid; t < KE * MM; t += 128) sW[t] = W_edge[t];
    if (tid < MM) sWo[tid] = w_out[tid];
    if (tid < 32) {
        sMu[tid] = rbf_mu[tid];
        float s = rbf_sigma[tid];
        sI2[tid] = 1.f / (2.f * s * s);
    }
    const float xi = xyz[i * 3 + 0];
    const float yi = xyz[i * 3 + 1];
    const float zi = xyz[i * 3 + 2];

    // ---- deterministic compaction: thread owns 8 consecutive j ----
    const float4* Prow = reinterpret_cast<const float4*>(P + (size_t)i * L);
    float4 pa = Prow[tid * 2], pb = Prow[tid * 2 + 1];
    float pv[8] = {pa.x, pa.y, pa.z, pa.w, pb.x, pb.y, pb.z, pb.w};
    int myj[8]; float myp[8]; int c = 0;
    const int jb = tid * 8;
    #pragma unroll
    for (int r = 0; r < 8; r++) {
        int j = jb + r;
        bool bb = (j == i + 1);
        bool ct = (pv[r] > 0.2f) && (j > i + 2);
        if (bb || ct) { myj[c] = j; myp[c] = bb ? 1.f : pv[r]; c++; }
    }
    int inc = c;
    #pragma unroll
    for (int off = 1; off < 32; off <<= 1) {
        int v = __shfl_up_sync(0xffffffffu, inc, off);
        if (lane >= off) inc += v;
    }
    if (lane == 31) wsum[wrp] = inc;
    __syncthreads();
    int offset = inc - c;
    int total  = 0;
    #pragma unroll
    for (int q = 0; q < 4; q++) {
        int wv = wsum[q];
        if (q < wrp) offset += wv;
        total += wv;
    }
    for (int t = 0; t < c; t++) { sList[offset + t] = myj[t]; sPij[offset + t] = myp[t]; }
    __syncthreads();

    const int ntch   = (total + 15) >> 4;   // 16-edge chunks
    const int padded = ntch << 4;

    // ---- per-edge geometry into smem (padded slots zeroed, j=0) ----
    for (int e = tid; e < padded; e += 128) {
        if (e < total) {
            int j = sList[e];
            float dx = xyz[3 * j + 0] - xi;
            float dy = xyz[3 * j + 1] - yi;
            float dz = xyz[3 * j + 2] - zi;
            sDx[e] = dx; sDy[e] = dy; sDz[e] = dz;
            sD[e]  = sqrtf(fmaf(dx, dx, fmaf(dy, dy, fmaf(dz, dz, 1e-12f))));
        } else {
            sList[e] = 0; sPij[e] = 0.f;
            sDx[e] = 0.f; sDy[e] = 0.f; sDz[e] = 0.f; sD[e] = 0.f;
        }
    }
    __syncthreads();

    // ---- main loop: warp-independent 16-edge chunks ----
    float ax = 0.f, ay = 0.f, az = 0.f;
    const int p = lane & 1;                 // m-half parity

    for (int cI = wrp; cI < ntch; cI += 4) {
        const int le = (cI << 4) + (lane >> 1);
        const int j    = sList[le];
        const float pij = sPij[le];
        const float dxv = sDx[le], dyv = sDy[le], dzv = sDz[le];
        const float dd  = sD[le];
        const float et  = (j == i + 1) ? 0.f : 1.f;

        // acc init from node projection (interleaved-m gather: 1 line/inst-pair)
        u64 acc[16];
        const float* nb = g_nb + j * MM + p * 4;
        #pragma unroll
        for (int q = 0; q < 8; q++) {
            ulonglong2 v = *reinterpret_cast<const ulonglong2*>(nb + q * 8);
            acc[2 * q] = v.x; acc[2 * q + 1] = v.y;
        }

        // k = 0 (etype), k = 1 (pij)
        {
            u64 uk = pack2(et, et);
            const float* wb = sW + p * 4;
            #pragma unroll
            for (int q = 0; q < 8; q++) {
                ulonglong2 wv = *reinterpret_cast<const ulonglong2*>(wb + q * 8);
                acc[2 * q]     = ffma2(uk, wv.x, acc[2 * q]);
                acc[2 * q + 1] = ffma2(uk, wv.y, acc[2 * q + 1]);
            }
        }
        {
            u64 uk = pack2(pij, pij);
            const float* wb = sW + MM + p * 4;
            #pragma unroll
            for (int q = 0; q < 8; q++) {
                ulonglong2 wv = *reinterpret_cast<const ulonglong2*>(wb + q * 8);
                acc[2 * q]     = ffma2(uk, wv.x, acc[2 * q]);
                acc[2 * q + 1] = ffma2(uk, wv.y, acc[2 * q + 1]);
            }
        }
        // k = 2..33 : RBF features
        #pragma unroll
        for (int k = 0; k < 32; k++) {
            float t = dd - sMu[k];
            float u = __expf(-t * t * sI2[k]);
            u64 uk = pack2(u, u);
            const float* wb = sW + (k + 2) * MM + p * 4;
            #pragma unroll
            for (int q = 0; q < 8; q++) {
                ulonglong2 wv = *reinterpret_cast<const ulonglong2*>(wb + q * 8);
                acc[2 * q]     = ffma2(uk, wv.x, acc[2 * q]);
                acc[2 * q + 1] = ffma2(uk, wv.y, acc[2 * q + 1]);
            }
        }

        // epilogue: relu . w_out over this lane's 32 m, combine pair, gate
        float gg = 0.f;
        #pragma unroll
        for (int q = 0; q < 8; q++) {
            float4 wo = *reinterpret_cast<const float4*>(sWo + q * 8 + p * 4);
            float2 a = unpack2(acc[2 * q]);
            float2 b = unpack2(acc[2 * q + 1]);
            gg = fmaf(fmaxf(a.x, 0.f), wo.x,
                 fmaf(fmaxf(a.y, 0.f), wo.y,
                 fmaf(fmaxf(b.x, 0.f), wo.z,
                 fmaf(fmaxf(b.y, 0.f), wo.w, gg))));
        }
        gg += __shfl_xor_sync(0xffffffffu, gg, 1);
        if (p == 0 && le < total) {
            float gate = 1.f / (1.f + __expf(-gg));
            ax = fmaf(gate, dxv, ax);
            ay = fmaf(gate, dyv, ay);
            az = fmaf(gate, dzv, az);
        }
    }

    // ---- deterministic block reduction ----
    #pragma unroll
    for (int off = 16; off; off >>= 1) {
        ax += __shfl_down_sync(0xffffffffu, ax, off);
        ay += __shfl_down_sync(0xffffffffu, ay, off);
        az += __shfl_down_sync(0xffffffffu, az, off);
    }
    if (lane == 0) { sred[wrp][0] = ax; sred[wrp][1] = ay; sred[wrp][2] = az; }
    __syncthreads();
    if (tid == 0) {
        float tx = 0.f, ty = 0.f, tz = 0.f;
        #pragma unroll
        for (int q = 0; q < 4; q++) { tx += sred[q][0]; ty += sred[q][1]; tz += sred[q][2]; }
        out[i * 3 + 0] = xi + tx;
        out[i * 3 + 1] = yi + ty;
        out[i * 3 + 2] = zi + tz;
    }
}

// ---------------------------------------------------------------------------
extern "C" void kernel_launch(void* const* d_in, const int* in_sizes, int n_in,
                              void* d_out, int out_size)
{
    const float* S         = (const float*)d_in[0];
    const float* P         = (const float*)d_in[1];
    const float* xyz       = (const float*)d_in[2];
    const float* rbf_mu    = (const float*)d_in[3];
    const float* rbf_sigma = (const float*)d_in[4];
    const float* W_edge    = (const float*)d_in[5];
    const float* b_edge    = (const float*)d_in[6];
    const float* W_node    = (const float*)d_in[7];
    const float* w_out     = (const float*)d_in[8];
    float* out = (float*)d_out;

    int L = in_sizes[2] / 3;          // 1024
    int D = in_sizes[0] / L;          // 640

    node_proj_kernel<<<L / 8, 256>>>(S, W_node, b_edge, L, D);
    edge_kernel<<<L, 128>>>(P, xyz, rbf_mu, rbf_sigma, W_edge, w_out, out, L);
}

// round 5
// speedup vs baseline: 7.7218x; 7.7218x over previous
#include <cuda_runtime.h>

// Shapes fixed by the problem: L=1024, D=640, K=32, M=64
#define LMAX 1024
#define MM   64
#define NT   4096          // RBF table points, d in [0, 64), h = 1/64
#define TSCALE 64.0f

// scratch (L2-resident): node projection + RBF-projection table
__device__ float g_nb[LMAX * MM];     // 256 KB
__device__ float g_T[NT * MM];        // 1 MB

// ---------------------------------------------------------------------------
// Kernel 0: T[t][m] = sum_k exp(-(g_t-mu_k)^2/(2 sig_k^2)) * W_edge[k+2][m]
// grid 4096, block 64
// ---------------------------------------------------------------------------
__global__ void __launch_bounds__(64) table_kernel(
    const float* __restrict__ rbf_mu,
    const float* __restrict__ rbf_sigma,
    const float* __restrict__ W_edge)
{
    __shared__ float se[32];
    const int t = blockIdx.x;
    const int m = threadIdx.x;
    if (m < 32) {
        float g  = (float)t * (1.0f / TSCALE);
        float mu = rbf_mu[m];
        float s  = rbf_sigma[m];
        float dd = g - mu;
        se[m] = __expf(-dd * dd / (2.0f * s * s));
    }
    __syncthreads();
    float acc = 0.f;
    #pragma unroll
    for (int k = 0; k < 32; k++)
        acc = fmaf(se[k], W_edge[(k + 2) * MM + m], acc);
    g_T[t * MM + m] = acc;
}

// ---------------------------------------------------------------------------
// Kernel 1: nb[j,m] = sum_d S[j,d] * W_node[d,m] + b_edge[m]
// 128 blocks x 8 rows, 256 threads, register double-buffered staging
// ---------------------------------------------------------------------------
__global__ void __launch_bounds__(256) node_proj_kernel(
    const float* __restrict__ S,
    const float* __restrict__ W_node,
    const float* __restrict__ b_edge,
    int L, int D)
{
    const int m  = threadIdx.x & 63;
    const int jr = threadIdx.x >> 6;     // 0..3
    const int j0 = blockIdx.x * 8;

    __shared__ float sS[8][64];
    __shared__ float sW[64][65];

    float a0 = 0.f, a1 = 0.f;
    float wreg[16], s0, s1;

    s0 = S[(size_t)(j0 + jr) * D + m];
    s1 = S[(size_t)(j0 + jr + 4) * D + m];
    #pragma unroll
    for (int r = 0; r < 16; r++)
        wreg[r] = W_node[(size_t)(r * 4 + jr) * MM + m];

    for (int d0 = 0; d0 < D; d0 += 64) {
        sS[jr][m]     = s0;
        sS[jr + 4][m] = s1;
        #pragma unroll
        for (int r = 0; r < 16; r++)
            sW[r * 4 + jr][m] = wreg[r];
        __syncthreads();
        int dn = d0 + 64;
        if (dn < D) {
            s0 = S[(size_t)(j0 + jr) * D + dn + m];
            s1 = S[(size_t)(j0 + jr + 4) * D + dn + m];
            #pragma unroll
            for (int r = 0; r < 16; r++)
                wreg[r] = W_node[(size_t)(dn + r * 4 + jr) * MM + m];
        }
        #pragma unroll
        for (int d = 0; d < 64; d++) {
            float w = sW[d][m];
            a0 = fmaf(sS[jr][d], w, a0);
            a1 = fmaf(sS[jr + 4][d], w, a1);
        }
        __syncthreads();
    }
    float b = b_edge[m];
    g_nb[(j0 + jr) * MM + m]     = a0 + b;
    g_nb[(j0 + jr + 4) * MM + m] = a1 + b;
}

// ---------------------------------------------------------------------------
// Kernel 2: one row per block, 256 threads, one edge per thread-iteration.
// msg = nb_j + et*W0 + pij*W1 + lerp(T, d); gate = sigmoid(relu(msg).wo)
// ---------------------------------------------------------------------------
__global__ void __launch_bounds__(256) edge_kernel(
    const float* __restrict__ P,
    const float* __restrict__ xyz,
    const float* __restrict__ W_edge,
    const float* __restrict__ w_out,
    float* __restrict__ out,
    int L)
{
    __shared__ __align__(16) float sW0[MM], sW1[MM], sWo[MM];
    __shared__ int   sList[LMAX];
    __shared__ float sPij[LMAX];
    __shared__ int   wsum[8];
    __shared__ float sred[8][3];

    const int tid  = threadIdx.x;
    const int lane = tid & 31;
    const int wrp  = tid >> 5;
    const int i    = blockIdx.x;

    if (tid < MM) {
        sW0[tid] = W_edge[tid];            // k=0 row (etype)
        sW1[tid] = W_edge[MM + tid];       // k=1 row (pij)
        sWo[tid] = w_out[tid];
    }
    const float xi = xyz[i * 3 + 0];
    const float yi = xyz[i * 3 + 1];
    const float zi = xyz[i * 3 + 2];

    // ---- deterministic compaction: thread owns 4 consecutive j ----
    const float4 p4 = reinterpret_cast<const float4*>(P + (size_t)i * L)[tid];
    float pv[4] = {p4.x, p4.y, p4.z, p4.w};
    int myj[4]; float myp[4]; int c = 0;
    const int jb = tid * 4;
    #pragma unroll
    for (int r = 0; r < 4; r++) {
        int j = jb + r;
        bool bb = (j == i + 1);
        bool ct = (pv[r] > 0.2f) && (j > i + 2);
        if (bb || ct) { myj[c] = j; myp[c] = bb ? 1.f : pv[r]; c++; }
    }
    int inc = c;
    #pragma unroll
    for (int off = 1; off < 32; off <<= 1) {
        int v = __shfl_up_sync(0xffffffffu, inc, off);
        if (lane >= off) inc += v;
    }
    if (lane == 31) wsum[wrp] = inc;
    __syncthreads();
    int offset = inc - c;
    int total  = 0;
    #pragma unroll
    for (int q = 0; q < 8; q++) {
        int wv = wsum[q];
        if (q < wrp) offset += wv;
        total += wv;
    }
    for (int t = 0; t < c; t++) { sList[offset + t] = myj[t]; sPij[offset + t] = myp[t]; }
    __syncthreads();

    // ---- per-edge fused compute, one edge per thread ----
    float ax = 0.f, ay = 0.f, az = 0.f;
    for (int e = tid; e < total; e += 256) {
        const int   j   = sList[e];
        const float pij = sPij[e];
        const float et  = (j == i + 1) ? 0.f : 1.f;
        const float dx = xyz[3 * j + 0] - xi;
        const float dy = xyz[3 * j + 1] - yi;
        const float dz = xyz[3 * j + 2] - zi;
        const float d  = sqrtf(fmaf(dx, dx, fmaf(dy, dy, fmaf(dz, dz, 1e-12f))));

        float tf = fminf(d * TSCALE, (float)(NT - 1));
        int   it = (int)tf;
        it = (it > NT - 2) ? (NT - 2) : it;
        const float w = tf - (float)it;

        const float4* nbp = reinterpret_cast<const float4*>(g_nb + j * MM);
        const float4* t0p = reinterpret_cast<const float4*>(g_T + it * MM);
        const float4* t1p = reinterpret_cast<const float4*>(g_T + (it + 1) * MM);
        const float4* w0p = reinterpret_cast<const float4*>(sW0);
        const float4* w1p = reinterpret_cast<const float4*>(sW1);
        const float4* wop = reinterpret_cast<const float4*>(sWo);

        float g = 0.f;
        #pragma unroll 4
        for (int mc = 0; mc < 16; mc++) {
            float4 nb = nbp[mc];
            float4 t0 = t0p[mc];
            float4 t1 = t1p[mc];
            float4 w0 = w0p[mc];
            float4 w1 = w1p[mc];
            float4 wo = wop[mc];

            float m0 = fmaf(et, w0.x, nb.x);
            float m1 = fmaf(et, w0.y, nb.y);
            float m2 = fmaf(et, w0.z, nb.z);
            float m3 = fmaf(et, w0.w, nb.w);
            m0 = fmaf(pij, w1.x, m0) + t0.x;
            m1 = fmaf(pij, w1.y, m1) + t0.y;
            m2 = fmaf(pij, w1.z, m2) + t0.z;
            m3 = fmaf(pij, w1.w, m3) + t0.w;
            m0 = fmaf(w, t1.x - t0.x, m0);
            m1 = fmaf(w, t1.y - t0.y, m1);
            m2 = fmaf(w, t1.z - t0.z, m2);
            m3 = fmaf(w, t1.w - t0.w, m3);
            g = fmaf(fmaxf(m0, 0.f), wo.x, g);
            g = fmaf(fmaxf(m1, 0.f), wo.y, g);
            g = fmaf(fmaxf(m2, 0.f), wo.z, g);
            g = fmaf(fmaxf(m3, 0.f), wo.w, g);
        }
        const float gate = 1.f / (1.f + __expf(-g));
        ax = fmaf(gate, dx, ax);
        ay = fmaf(gate, dy, ay);
        az = fmaf(gate, dz, az);
    }

    // ---- deterministic block reduction ----
    #pragma unroll
    for (int off = 16; off; off >>= 1) {
        ax += __shfl_down_sync(0xffffffffu, ax, off);
        ay += __shfl_down_sync(0xffffffffu, ay, off);
        az += __shfl_down_sync(0xffffffffu, az, off);
    }
    if (lane == 0) { sred[wrp][0] = ax; sred[wrp][1] = ay; sred[wrp][2] = az; }
    __syncthreads();
    if (tid == 0) {
        float tx = 0.f, ty = 0.f, tz = 0.f;
        #pragma unroll
        for (int q = 0; q < 8; q++) { tx += sred[q][0]; ty += sred[q][1]; tz += sred[q][2]; }
        out[i * 3 + 0] = xi + tx;
        out[i * 3 + 1] = yi + ty;
        out[i * 3 + 2] = zi + tz;
    }
}

// ---------------------------------------------------------------------------
extern "C" void kernel_launch(void* const* d_in, const int* in_sizes, int n_in,
                              void* d_out, int out_size)
{
    const float* S         = (const float*)d_in[0];
    const float* P         = (const float*)d_in[1];
    const float* xyz       = (const float*)d_in[2];
    const float* rbf_mu    = (const float*)d_in[3];
    const float* rbf_sigma = (const float*)d_in[4];
    const float* W_edge    = (const float*)d_in[5];
    const float* b_edge    = (const float*)d_in[6];
    const float* W_node    = (const float*)d_in[7];
    const float* w_out     = (const float*)d_in[8];
    float* out = (float*)d_out;

    int L = in_sizes[2] / 3;          // 1024
    int D = in_sizes[0] / L;          // 640

    table_kernel<<<NT, 64>>>(rbf_mu, rbf_sigma, W_edge);
    node_proj_kernel<<<L / 8, 256>>>(S, W_node, b_edge, L, D);
    edge_kernel<<<L, 256>>>(P, xyz, W_edge, w_out, out, L);
}

// round 6
// speedup vs baseline: 16.5606x; 2.1447x over previous
#include <cuda_runtime.h>
#include <cuda_fp16.h>

// Shapes fixed by the problem: L=1024, D=640, K=32, M=64
#define LMAX 1024
#define MM   64
#define NT   16384         // RBF table rows, d in [0, 64), h = 1/256
#define TSCALE 256.0f

// fp16 scratch (L1/L2-resident)
__device__ __half g_nb16[LMAX * MM];   // 128 KB  (node proj + bias)
__device__ __half g_T16[NT * MM];      // 2 MB    (RBF @ W_edge[2:34])

// ---------------------------------------------------------------------------
// Kernel 0: T[t][m] = sum_k exp(-(t/256-mu_k)^2/(2 sig_k^2)) * W_edge[k+2][m]
// grid 256 blocks x 64 t-rows, 256 threads
// ---------------------------------------------------------------------------
__global__ void __launch_bounds__(256) table_kernel(
    const float* __restrict__ rbf_mu,
    const float* __restrict__ rbf_sigma,
    const float* __restrict__ W_edge)
{
    __shared__ float se[64][32];
    __shared__ float sw[32][64];
    const int tid = threadIdx.x;
    const int t0  = blockIdx.x * 64;

    for (int v = tid; v < 32 * 64; v += 256)
        sw[v >> 6][v & 63] = W_edge[2 * MM + v];
    for (int v = tid; v < 64 * 32; v += 256) {
        int t = v >> 5, k = v & 31;
        float g  = (float)(t0 + t) * (1.0f / TSCALE);
        float mu = rbf_mu[k];
        float s  = rbf_sigma[k];
        float dd = g - mu;
        se[t][k] = __expf(-dd * dd / (2.0f * s * s));
    }
    __syncthreads();

    const int m  = tid & 63;
    const int tb = (tid >> 6) * 16;
    #pragma unroll 4
    for (int r = 0; r < 16; r++) {
        float acc = 0.f;
        #pragma unroll
        for (int k = 0; k < 32; k++)
            acc = fmaf(se[tb + r][k], sw[k][m], acc);
        g_T16[(size_t)(t0 + tb + r) * MM + m] = __float2half_rn(acc);
    }
}

// ---------------------------------------------------------------------------
// Kernel 1: nb16[j,m] = fp16( sum_d S[j,d]*W_node[d,m] + b_edge[m] )
// ---------------------------------------------------------------------------
__global__ void __launch_bounds__(256) node_proj_kernel(
    const float* __restrict__ S,
    const float* __restrict__ W_node,
    const float* __restrict__ b_edge,
    int L, int D)
{
    const int m  = threadIdx.x & 63;
    const int jr = threadIdx.x >> 6;
    const int j0 = blockIdx.x * 8;

    __shared__ float sS[8][64];
    __shared__ float sW[64][65];

    float a0 = 0.f, a1 = 0.f;
    float wreg[16], s0, s1;

    s0 = S[(size_t)(j0 + jr) * D + m];
    s1 = S[(size_t)(j0 + jr + 4) * D + m];
    #pragma unroll
    for (int r = 0; r < 16; r++)
        wreg[r] = W_node[(size_t)(r * 4 + jr) * MM + m];

    for (int d0 = 0; d0 < D; d0 += 64) {
        sS[jr][m]     = s0;
        sS[jr + 4][m] = s1;
        #pragma unroll
        for (int r = 0; r < 16; r++)
            sW[r * 4 + jr][m] = wreg[r];
        __syncthreads();
        int dn = d0 + 64;
        if (dn < D) {
            s0 = S[(size_t)(j0 + jr) * D + dn + m];
            s1 = S[(size_t)(j0 + jr + 4) * D + dn + m];
            #pragma unroll
            for (int r = 0; r < 16; r++)
                wreg[r] = W_node[(size_t)(dn + r * 4 + jr) * MM + m];
        }
        #pragma unroll
        for (int d = 0; d < 64; d++) {
            float w = sW[d][m];
            a0 = fmaf(sS[jr][d], w, a0);
            a1 = fmaf(sS[jr + 4][d], w, a1);
        }
        __syncthreads();
    }
    float b = b_edge[m];
    g_nb16[(j0 + jr) * MM + m]     = __float2half_rn(a0 + b);
    g_nb16[(j0 + jr + 4) * MM + m] = __float2half_rn(a1 + b);
}

// ---------------------------------------------------------------------------
// Kernel 2: grid 512, block 256; block b does rows b and 1023-b.
// 8 lanes per edge (4 edges/warp): lane sub owns m = sub*8..sub*8+7.
// Per edge: 1 fp16 nb row (1 line) + 1 fp16 T row (1 line) -> 2 wavefronts.
// ---------------------------------------------------------------------------
__global__ void __launch_bounds__(256, 3) edge_kernel(
    const float* __restrict__ P,
    const float* __restrict__ xyz,
    const float* __restrict__ W_edge,
    const float* __restrict__ w_out,
    float* __restrict__ out,
    int L)
{
    __shared__ int   sList[LMAX];
    __shared__ float sPij[LMAX];
    __shared__ int   sIt[LMAX];
    __shared__ float sDx[LMAX], sDy[LMAX], sDz[LMAX];
    __shared__ int   wsum[8];
    __shared__ float sred[8][3];

    const int tid  = threadIdx.x;
    const int lane = tid & 31;
    const int wrp  = tid >> 5;
    const int sub  = lane & 7;    // m-slice
    const int es   = lane >> 3;   // edge slot within 4-edge chunk

    // per-lane weight slices (registers, loaded once)
    const int mb = sub * 8;
    float w0r[8], w1r[8], wor[8];
    {
        float4 a = *(const float4*)(W_edge + mb);
        float4 b = *(const float4*)(W_edge + mb + 4);
        float4 c = *(const float4*)(W_edge + MM + mb);
        float4 d = *(const float4*)(W_edge + MM + mb + 4);
        float4 e = *(const float4*)(w_out + mb);
        float4 f = *(const float4*)(w_out + mb + 4);
        w0r[0]=a.x; w0r[1]=a.y; w0r[2]=a.z; w0r[3]=a.w;
        w0r[4]=b.x; w0r[5]=b.y; w0r[6]=b.z; w0r[7]=b.w;
        w1r[0]=c.x; w1r[1]=c.y; w1r[2]=c.z; w1r[3]=c.w;
        w1r[4]=d.x; w1r[5]=d.y; w1r[6]=d.z; w1r[7]=d.w;
        wor[0]=e.x; wor[1]=e.y; wor[2]=e.z; wor[3]=e.w;
        wor[4]=f.x; wor[5]=f.y; wor[6]=f.z; wor[7]=f.w;
    }

    for (int half = 0; half < 2; half++) {
        const int i = half ? (L - 1 - (int)blockIdx.x) : (int)blockIdx.x;
        __syncthreads();   // smem reuse across halves

        const float xi = xyz[i * 3 + 0];
        const float yi = xyz[i * 3 + 1];
        const float zi = xyz[i * 3 + 2];

        // ---- deterministic compaction: thread owns 4 consecutive j ----
        const float4 p4 = reinterpret_cast<const float4*>(P + (size_t)i * L)[tid];
        float pv[4] = {p4.x, p4.y, p4.z, p4.w};
        int myj[4]; float myp[4]; int c = 0;
        const int jb = tid * 4;
        #pragma unroll
        for (int r = 0; r < 4; r++) {
            int j = jb + r;
            bool bb = (j == i + 1);
            bool ct = (pv[r] > 0.2f) && (j > i + 2);
            if (bb || ct) { myj[c] = j; myp[c] = bb ? 1.f : pv[r]; c++; }
        }
        int inc = c;
        #pragma unroll
        for (int off = 1; off < 32; off <<= 1) {
            int v = __shfl_up_sync(0xffffffffu, inc, off);
            if (lane >= off) inc += v;
        }
        if (lane == 31) wsum[wrp] = inc;
        __syncthreads();
        int offset = inc - c;
        int total  = 0;
        #pragma unroll
        for (int q = 0; q < 8; q++) {
            int wv = wsum[q];
            if (q < wrp) offset += wv;
            total += wv;
        }
        for (int t = 0; t < c; t++) { sList[offset + t] = myj[t]; sPij[offset + t] = myp[t]; }
        __syncthreads();

        const int padded = (total + 31) & ~31;

        // ---- per-edge geometry + table index ----
        for (int e = tid; e < padded; e += 256) {
            if (e < total) {
                int j = sList[e];
                float dx = xyz[3 * j + 0] - xi;
                float dy = xyz[3 * j + 1] - yi;
                float dz = xyz[3 * j + 2] - zi;
                float d  = sqrtf(fmaf(dx, dx, fmaf(dy, dy, fmaf(dz, dz, 1e-12f))));
                int it = (int)(d * TSCALE + 0.5f);
                sIt[e] = (it > NT - 1) ? (NT - 1) : it;
                sDx[e] = dx; sDy[e] = dy; sDz[e] = dz;
            } else {
                sList[e] = 0; sPij[e] = 0.f; sIt[e] = 0;
                sDx[e] = 0.f; sDy[e] = 0.f; sDz[e] = 0.f;
            }
        }
        __syncthreads();

        // ---- main loop: 4 edges per warp-iteration ----
        float ax = 0.f, ay = 0.f, az = 0.f;
        for (int eb = wrp * 4; eb < padded; eb += 32) {
            const int e    = eb + es;
            const int j    = sList[e];
            const float pij = sPij[e];
            const int  it  = sIt[e];
            const float et = (j == i + 1) ? 0.f : 1.f;

            uint4 nbv = *reinterpret_cast<const uint4*>(g_nb16 + j * MM + mb);
            uint4 tv  = *reinterpret_cast<const uint4*>(g_T16 + (size_t)it * MM + mb);
            const __half2* nh = reinterpret_cast<const __half2*>(&nbv);
            const __half2* th = reinterpret_cast<const __half2*>(&tv);

            float g = 0.f;
            #pragma unroll
            for (int q = 0; q < 4; q++) {
                float2 nf = __half22float2(nh[q]);
                float2 tf = __half22float2(th[q]);
                float a0 = nf.x + fmaf(et, w0r[2 * q],     fmaf(pij, w1r[2 * q],     tf.x));
                float a1 = nf.y + fmaf(et, w0r[2 * q + 1], fmaf(pij, w1r[2 * q + 1], tf.y));
                g = fmaf(fmaxf(a0, 0.f), wor[2 * q], g);
                g = fmaf(fmaxf(a1, 0.f), wor[2 * q + 1], g);
            }
            // reduce over the 8 lanes of this edge
            g += __shfl_xor_sync(0xffffffffu, g, 1);
            g += __shfl_xor_sync(0xffffffffu, g, 2);
            g += __shfl_xor_sync(0xffffffffu, g, 4);

            if (sub == 0 && e < total) {
                float ex = __expf(-g);
                float gate = __fdividef(1.f, 1.f + ex);
                ax = fmaf(gate, sDx[e], ax);
                ay = fmaf(gate, sDy[e], ay);
                az = fmaf(gate, sDz[e], az);
            }
        }

        // ---- deterministic block reduction ----
        #pragma unroll
        for (int off = 16; off; off >>= 1) {
            ax += __shfl_down_sync(0xffffffffu, ax, off);
            ay += __shfl_down_sync(0xffffffffu, ay, off);
            az += __shfl_down_sync(0xffffffffu, az, off);
        }
        if (lane == 0) { sred[wrp][0] = ax; sred[wrp][1] = ay; sred[wrp][2] = az; }
        __syncthreads();
        if (tid == 0) {
            float tx = 0.f, ty = 0.f, tz = 0.f;
            #pragma unroll
            for (int q = 0; q < 8; q++) { tx += sred[q][0]; ty += sred[q][1]; tz += sred[q][2]; }
            out[i * 3 + 0] = xi + tx;
            out[i * 3 + 1] = yi + ty;
            out[i * 3 + 2] = zi + tz;
        }
    }
}

// ---------------------------------------------------------------------------
extern "C" void kernel_launch(void* const* d_in, const int* in_sizes, int n_in,
                              void* d_out, int out_size)
{
    const float* S         = (const float*)d_in[0];
    const float* P         = (const float*)d_in[1];
    const float* xyz       = (const float*)d_in[2];
    const float* rbf_mu    = (const float*)d_in[3];
    const float* rbf_sigma = (const float*)d_in[4];
    const float* W_edge    = (const float*)d_in[5];
    const float* b_edge    = (const float*)d_in[6];
    const float* W_node    = (const float*)d_in[7];
    const float* w_out     = (const float*)d_in[8];
    float* out = (float*)d_out;

    int L = in_sizes[2] / 3;          // 1024
    int D = in_sizes[0] / L;          // 640

    table_kernel<<<NT / 64, 256>>>(rbf_mu, rbf_sigma, W_edge);
    node_proj_kernel<<<L / 8, 256>>>(S, W_node, b_edge, L, D);
    edge_kernel<<<L / 2, 256>>>(P, xyz, W_edge, w_out, out, L);
}

// round 7
// speedup vs baseline: 17.2115x; 1.0393x over previous
#include <cuda_runtime.h>
#include <cuda_fp16.h>

// Shapes fixed by the problem: L=1024, D=640, K=32, M=64
#define LMAX 1024
#define MM   64
#define NT   16384         // RBF table rows, d in [0, 64), h = 1/256
#define TSCALE 256.0f

// fp16 scratch (L1/L2-resident)
__device__ __half g_nb16[LMAX * MM];   // 128 KB  (node proj + bias)
__device__ __half g_T16[NT * MM];      // 2 MB    (RBF @ W_edge[2:34])

// ---------------------------------------------------------------------------
// Fused prep kernel:
//   blocks [0,128)    : node projection, 8 rows each
//   blocks [128,1152) : RBF table, 16 t-rows each (4 independent chains/thread)
// ---------------------------------------------------------------------------
__global__ void __launch_bounds__(256) prep_kernel(
    const float* __restrict__ S,
    const float* __restrict__ W_node,
    const float* __restrict__ b_edge,
    const float* __restrict__ rbf_mu,
    const float* __restrict__ rbf_sigma,
    const float* __restrict__ W_edge,
    int L, int D)
{
    __shared__ __align__(16) float sbuf[4672];   // 18688 B, shared by both paths
    const int tid = threadIdx.x;

    if (blockIdx.x < 128) {
        // ---------------- node projection ----------------
        float (*sS)[64] = reinterpret_cast<float (*)[64]>(sbuf);          // 8 x 64
        float (*sW)[65] = reinterpret_cast<float (*)[65]>(sbuf + 512);    // 64 x 65

        const int m  = tid & 63;
        const int jr = tid >> 6;
        const int j0 = blockIdx.x * 8;

        float a0 = 0.f, a1 = 0.f;
        float wreg[16], s0, s1;

        s0 = S[(size_t)(j0 + jr) * D + m];
        s1 = S[(size_t)(j0 + jr + 4) * D + m];
        #pragma unroll
        for (int r = 0; r < 16; r++)
            wreg[r] = W_node[(size_t)(r * 4 + jr) * MM + m];

        for (int d0 = 0; d0 < D; d0 += 64) {
            sS[jr][m]     = s0;
            sS[jr + 4][m] = s1;
            #pragma unroll
            for (int r = 0; r < 16; r++)
                sW[r * 4 + jr][m] = wreg[r];
            __syncthreads();
            int dn = d0 + 64;
            if (dn < D) {
                s0 = S[(size_t)(j0 + jr) * D + dn + m];
                s1 = S[(size_t)(j0 + jr + 4) * D + dn + m];
                #pragma unroll
                for (int r = 0; r < 16; r++)
                    wreg[r] = W_node[(size_t)(dn + r * 4 + jr) * MM + m];
            }
            #pragma unroll
            for (int d = 0; d < 64; d++) {
                float w = sW[d][m];
                a0 = fmaf(sS[jr][d], w, a0);
                a1 = fmaf(sS[jr + 4][d], w, a1);
            }
            __syncthreads();
        }
        float b = b_edge[m];
        g_nb16[(j0 + jr) * MM + m]     = __float2half_rn(a0 + b);
        g_nb16[(j0 + jr + 4) * MM + m] = __float2half_rn(a1 + b);
    } else {
        // ---------------- RBF table ----------------
        float* se = sbuf;           // 16 x 32
        float* sw = sbuf + 512;     // 32 x 64
        const int t0 = (blockIdx.x - 128) * 16;

        for (int v = tid; v < 32 * 64; v += 256)
            sw[v] = W_edge[2 * MM + v];
        for (int v = tid; v < 16 * 32; v += 256) {
            int t = v >> 5, k = v & 31;
            float g  = (float)(t0 + t) * (1.0f / TSCALE);
            float mu = rbf_mu[k];
            float s  = rbf_sigma[k];
            float dd = g - mu;
            se[v] = __expf(-dd * dd / (2.0f * s * s));
        }
        __syncthreads();

        const int m  = tid & 63;
        const int tr = tid >> 6;          // 0..3
        float a0 = 0.f, a1 = 0.f, a2 = 0.f, a3 = 0.f;
        #pragma unroll
        for (int k = 0; k < 32; k++) {
            float w = sw[k * 64 + m];
            a0 = fmaf(se[(tr +  0) * 32 + k], w, a0);
            a1 = fmaf(se[(tr +  4) * 32 + k], w, a1);
            a2 = fmaf(se[(tr +  8) * 32 + k], w, a2);
            a3 = fmaf(se[(tr + 12) * 32 + k], w, a3);
        }
        g_T16[(size_t)(t0 + tr +  0) * MM + m] = __float2half_rn(a0);
        g_T16[(size_t)(t0 + tr +  4) * MM + m] = __float2half_rn(a1);
        g_T16[(size_t)(t0 + tr +  8) * MM + m] = __float2half_rn(a2);
        g_T16[(size_t)(t0 + tr + 12) * MM + m] = __float2half_rn(a3);
    }
}

// ---------------------------------------------------------------------------
// Kernel 2: grid 512, block 256; block b does rows b and 1023-b.
// 8 lanes per edge; each warp processes 8 edges per iteration (unroll-2,
// loads batched for MLP). launch_bounds(256,2) -> 128-reg cap, no spills.
// ---------------------------------------------------------------------------
__global__ void __launch_bounds__(256, 2) edge_kernel(
    const float* __restrict__ P,
    const float* __restrict__ xyz,
    const float* __restrict__ W_edge,
    const float* __restrict__ w_out,
    float* __restrict__ out,
    int L)
{
    __shared__ int   sList[LMAX];
    __shared__ float sPij[LMAX];
    __shared__ int   sIt[LMAX];
    __shared__ float sDx[LMAX], sDy[LMAX], sDz[LMAX];
    __shared__ int   wsum[8];
    __shared__ float sred[8][3];

    const int tid  = threadIdx.x;
    const int lane = tid & 31;
    const int wrp  = tid >> 5;
    const int sub  = lane & 7;    // m-slice within edge group
    const int es   = lane >> 3;   // edge slot within 4-edge subchunk

    // per-lane weight slices (registers, loaded once)
    const int mb = sub * 8;
    float w0r[8], w1r[8], wor[8];
    {
        float4 a = *(const float4*)(W_edge + mb);
        float4 b = *(const float4*)(W_edge + mb + 4);
        float4 c = *(const float4*)(W_edge + MM + mb);
        float4 d = *(const float4*)(W_edge + MM + mb + 4);
        float4 e = *(const float4*)(w_out + mb);
        float4 f = *(const float4*)(w_out + mb + 4);
        w0r[0]=a.x; w0r[1]=a.y; w0r[2]=a.z; w0r[3]=a.w;
        w0r[4]=b.x; w0r[5]=b.y; w0r[6]=b.z; w0r[7]=b.w;
        w1r[0]=c.x; w1r[1]=c.y; w1r[2]=c.z; w1r[3]=c.w;
        w1r[4]=d.x; w1r[5]=d.y; w1r[6]=d.z; w1r[7]=d.w;
        wor[0]=e.x; wor[1]=e.y; wor[2]=e.z; wor[3]=e.w;
        wor[4]=f.x; wor[5]=f.y; wor[6]=f.z; wor[7]=f.w;
    }

    for (int half = 0; half < 2; half++) {
        const int i = half ? (L - 1 - (int)blockIdx.x) : (int)blockIdx.x;
        __syncthreads();   // smem reuse across halves

        const float xi = xyz[i * 3 + 0];
        const float yi = xyz[i * 3 + 1];
        const float zi = xyz[i * 3 + 2];

        // ---- deterministic compaction: thread owns 4 consecutive j ----
        const float4 p4 = reinterpret_cast<const float4*>(P + (size_t)i * L)[tid];
        float pv[4] = {p4.x, p4.y, p4.z, p4.w};
        int myj[4]; float myp[4]; int c = 0;
        const int jb = tid * 4;
        #pragma unroll
        for (int r = 0; r < 4; r++) {
            int j = jb + r;
            bool bb = (j == i + 1);
            bool ct = (pv[r] > 0.2f) && (j > i + 2);
            if (bb || ct) { myj[c] = j; myp[c] = bb ? 1.f : pv[r]; c++; }
        }
        int inc = c;
        #pragma unroll
        for (int off = 1; off < 32; off <<= 1) {
            int v = __shfl_up_sync(0xffffffffu, inc, off);
            if (lane >= off) inc += v;
        }
        if (lane == 31) wsum[wrp] = inc;
        __syncthreads();
        int offset = inc - c;
        int total  = 0;
        #pragma unroll
        for (int q = 0; q < 8; q++) {
            int wv = wsum[q];
            if (q < wrp) offset += wv;
            total += wv;
        }
        for (int t = 0; t < c; t++) { sList[offset + t] = myj[t]; sPij[offset + t] = myp[t]; }
        __syncthreads();

        const int padded = (total + 63) & ~63;

        // ---- per-edge geometry + table index ----
        for (int e = tid; e < padded; e += 256) {
            if (e < total) {
                int j = sList[e];
                float dx = xyz[3 * j + 0] - xi;
                float dy = xyz[3 * j + 1] - yi;
                float dz = xyz[3 * j + 2] - zi;
                float d  = sqrtf(fmaf(dx, dx, fmaf(dy, dy, fmaf(dz, dz, 1e-12f))));
                int it = (int)(d * TSCALE + 0.5f);
                sIt[e] = (it > NT - 1) ? (NT - 1) : it;
                sDx[e] = dx; sDy[e] = dy; sDz[e] = dz;
            } else {
                sList[e] = 0; sPij[e] = 0.f; sIt[e] = 0;
                sDx[e] = 0.f; sDy[e] = 0.f; sDz[e] = 0.f;
            }
        }
        __syncthreads();

        // ---- main loop: 8 edges per warp-iteration (unroll-2) ----
        float ax = 0.f, ay = 0.f, az = 0.f;
        for (int eb = wrp * 8; eb < padded; eb += 64) {
            const int e1 = eb + es;
            const int e2 = eb + 4 + es;
            const int j1 = sList[e1],  j2 = sList[e2];
            const float p1 = sPij[e1], p2 = sPij[e2];
            const int it1 = sIt[e1],   it2 = sIt[e2];
            const float et1 = (j1 == i + 1) ? 0.f : 1.f;
            const float et2 = (j2 == i + 1) ? 0.f : 1.f;

            // batch all 4 loads up front (MLP = 4 per lane)
            uint4 nb1 = *reinterpret_cast<const uint4*>(g_nb16 + j1 * MM + mb);
            uint4 tv1 = *reinterpret_cast<const uint4*>(g_T16 + (size_t)it1 * MM + mb);
            uint4 nb2 = *reinterpret_cast<const uint4*>(g_nb16 + j2 * MM + mb);
            uint4 tv2 = *reinterpret_cast<const uint4*>(g_T16 + (size_t)it2 * MM + mb);

            const __half2* nh1 = reinterpret_cast<const __half2*>(&nb1);
            const __half2* th1 = reinterpret_cast<const __half2*>(&tv1);
            const __half2* nh2 = reinterpret_cast<const __half2*>(&nb2);
            const __half2* th2 = reinterpret_cast<const __half2*>(&tv2);

            float g1 = 0.f, g2 = 0.f;
            #pragma unroll
            for (int q = 0; q < 4; q++) {
                float2 nf1 = __half22float2(nh1[q]);
                float2 tf1 = __half22float2(th1[q]);
                float2 nf2 = __half22float2(nh2[q]);
                float2 tf2 = __half22float2(th2[q]);
                float w0a = w0r[2 * q], w0b = w0r[2 * q + 1];
                float w1a = w1r[2 * q], w1b = w1r[2 * q + 1];
                float woa = wor[2 * q], wob = wor[2 * q + 1];

                float a0 = nf1.x + fmaf(et1, w0a, fmaf(p1, w1a, tf1.x));
                float a1 = nf1.y + fmaf(et1, w0b, fmaf(p1, w1b, tf1.y));
                g1 = fmaf(fmaxf(a0, 0.f), woa, g1);
                g1 = fmaf(fmaxf(a1, 0.f), wob, g1);

                float b0 = nf2.x + fmaf(et2, w0a, fmaf(p2, w1a, tf2.x));
                float b1 = nf2.y + fmaf(et2, w0b, fmaf(p2, w1b, tf2.y));
                g2 = fmaf(fmaxf(b0, 0.f), woa, g2);
                g2 = fmaf(fmaxf(b1, 0.f), wob, g2);
            }
            // reduce over the 8 lanes of each edge group
            g1 += __shfl_xor_sync(0xffffffffu, g1, 1);
            g2 += __shfl_xor_sync(0xffffffffu, g2, 1);
            g1 += __shfl_xor_sync(0xffffffffu, g1, 2);
            g2 += __shfl_xor_sync(0xffffffffu, g2, 2);
            g1 += __shfl_xor_sync(0xffffffffu, g1, 4);
            g2 += __shfl_xor_sync(0xffffffffu, g2, 4);

            if (sub == 0) {
                if (e1 < total) {
                    float gate = __fdividef(1.f, 1.f + __expf(-g1));
                    ax = fmaf(gate, sDx[e1], ax);
                    ay = fmaf(gate, sDy[e1], ay);
                    az = fmaf(gate, sDz[e1], az);
                }
                if (e2 < total) {
                    float gate = __fdividef(1.f, 1.f + __expf(-g2));
                    ax = fmaf(gate, sDx[e2], ax);
                    ay = fmaf(gate, sDy[e2], ay);
                    az = fmaf(gate, sDz[e2], az);
                }
            }
        }

        // ---- deterministic block reduction ----
        #pragma unroll
        for (int off = 16; off; off >>= 1) {
            ax += __shfl_down_sync(0xffffffffu, ax, off);
            ay += __shfl_down_sync(0xffffffffu, ay, off);
            az += __shfl_down_sync(0xffffffffu, az, off);
        }
        if (lane == 0) { sred[wrp][0] = ax; sred[wrp][1] = ay; sred[wrp][2] = az; }
        __syncthreads();
        if (tid == 0) {
            float tx = 0.f, ty = 0.f, tz = 0.f;
            #pragma unroll
            for (int q = 0; q < 8; q++) { tx += sred[q][0]; ty += sred[q][1]; tz += sred[q][2]; }
            out[i * 3 + 0] = xi + tx;
            out[i * 3 + 1] = yi + ty;
            out[i * 3 + 2] = zi + tz;
        }
    }
}

// ---------------------------------------------------------------------------
extern "C" void kernel_launch(void* const* d_in, const int* in_sizes, int n_in,
                              void* d_out, int out_size)
{
    const float* S         = (const float*)d_in[0];
    const float* P         = (const float*)d_in[1];
    const float* xyz       = (const float*)d_in[2];
    const float* rbf_mu    = (const float*)d_in[3];
    const float* rbf_sigma = (const float*)d_in[4];
    const float* W_edge    = (const float*)d_in[5];
    const float* b_edge    = (const float*)d_in[6];
    const float* W_node    = (const float*)d_in[7];
    const float* w_out     = (const float*)d_in[8];
    float* out = (float*)d_out;

    int L = in_sizes[2] / 3;          // 1024
    int D = in_sizes[0] / L;          // 640

    prep_kernel<<<128 + NT / 16, 256>>>(S, W_node, b_edge,
                                        rbf_mu, rbf_sigma, W_edge, L, D);
    edge_kernel<<<L / 2, 256>>>(P, xyz, W_edge, w_out, out, L);
}

// round 8
// speedup vs baseline: 18.5541x; 1.0780x over previous
#include <cuda_runtime.h>
#include <cuda_fp16.h>

// Shapes fixed by the problem: L=1024, D=640, K=32, M=64
#define LMAX 1024
#define MM   64
#define NT   8192          // RBF table rows, d in [0, 64), h = 1/128
#define TSCALE 128.0f

// fp16 scratch (L1/L2-resident)
__device__ __half g_nb16[LMAX * MM];   // 128 KB  (node proj + bias)
__device__ __half g_T16[NT * MM];      // 1 MB    (w0 + RBF @ W_edge[2:34])

// ---------------------------------------------------------------------------
// Fused prep kernel:
//   blocks [0,128)   : node projection, 8 rows each
//   blocks [128,384) : RBF table, 32 t-rows each, W column in registers,
//                      acc initialized with w0 (etype row) baked in.
// ---------------------------------------------------------------------------
__global__ void __launch_bounds__(256) prep_kernel(
    const float* __restrict__ S,
    const float* __restrict__ W_node,
    const float* __restrict__ b_edge,
    const float* __restrict__ rbf_mu,
    const float* __restrict__ rbf_sigma,
    const float* __restrict__ W_edge,
    int L, int D)
{
    __shared__ __align__(16) float sbuf[4672];
    const int tid = threadIdx.x;

    if (blockIdx.x < 128) {
        // ---------------- node projection ----------------
        float (*sS)[64] = reinterpret_cast<float (*)[64]>(sbuf);          // 8 x 64
        float (*sW)[65] = reinterpret_cast<float (*)[65]>(sbuf + 512);    // 64 x 65

        const int m  = tid & 63;
        const int jr = tid >> 6;
        const int j0 = blockIdx.x * 8;

        float a0 = 0.f, a1 = 0.f;
        float wreg[16], s0, s1;

        s0 = S[(size_t)(j0 + jr) * D + m];
        s1 = S[(size_t)(j0 + jr + 4) * D + m];
        #pragma unroll
        for (int r = 0; r < 16; r++)
            wreg[r] = W_node[(size_t)(r * 4 + jr) * MM + m];

        for (int d0 = 0; d0 < D; d0 += 64) {
            sS[jr][m]     = s0;
            sS[jr + 4][m] = s1;
            #pragma unroll
            for (int r = 0; r < 16; r++)
                sW[r * 4 + jr][m] = wreg[r];
            __syncthreads();
            int dn = d0 + 64;
            if (dn < D) {
                s0 = S[(size_t)(j0 + jr) * D + dn + m];
                s1 = S[(size_t)(j0 + jr + 4) * D + dn + m];
                #pragma unroll
                for (int r = 0; r < 16; r++)
                    wreg[r] = W_node[(size_t)(dn + r * 4 + jr) * MM + m];
            }
            #pragma unroll
            for (int d = 0; d < 64; d++) {
                float w = sW[d][m];
                a0 = fmaf(sS[jr][d], w, a0);
                a1 = fmaf(sS[jr + 4][d], w, a1);
            }
            __syncthreads();
        }
        float b = b_edge[m];
        g_nb16[(j0 + jr) * MM + m]     = __float2half_rn(a0 + b);
        g_nb16[(j0 + jr + 4) * MM + m] = __float2half_rn(a1 + b);
    } else {
        // ---------------- RBF table (+w0 baked) ----------------
        float* se = sbuf;                       // 32 rows x 32 k
        const int t0   = (blockIdx.x - 128) * 32;
        const int m    = tid & 63;
        const int slot = tid >> 6;              // 0..3 -> rows slot*8..slot*8+7

        // exp features for 32 rows
        for (int v = tid; v < 32 * 32; v += 256) {
            int t = v >> 5, k = v & 31;
            float g  = (float)(t0 + t) * (1.0f / TSCALE);
            float mu = rbf_mu[k];
            float s  = rbf_sigma[k];
            float dd = g - mu;
            se[v] = __expf(-dd * dd / (2.0f * s * s));
        }
        // W column for this thread's m, in registers
        float wreg[32];
        #pragma unroll
        for (int k = 0; k < 32; k++)
            wreg[k] = W_edge[(k + 2) * MM + m];
        const float w0 = W_edge[m];
        __syncthreads();

        float acc[8];
        #pragma unroll
        for (int r = 0; r < 8; r++) acc[r] = w0;
        #pragma unroll
        for (int k = 0; k < 32; k++) {
            float w = wreg[k];
            #pragma unroll
            for (int r = 0; r < 8; r++)
                acc[r] = fmaf(se[(slot * 8 + r) * 32 + k], w, acc[r]);
        }
        #pragma unroll
        for (int r = 0; r < 8; r++)
            g_T16[(size_t)(t0 + slot * 8 + r) * MM + m] = __float2half_rn(acc[r]);
    }
}

// ---------------------------------------------------------------------------
// Kernel 2: grid 512, block 256; block b does rows b and 1023-b.
// Contacts only in the main loop (w0 baked into T'): msg = (nb+T') + pij*w1.
// 8 lanes per edge, 8 edges per warp-iteration. Backbone edge (1 per row)
// handled by warp 0 at the end.
// ---------------------------------------------------------------------------
__global__ void __launch_bounds__(256, 3) edge_kernel(
    const float* __restrict__ P,
    const float* __restrict__ xyz,
    const float* __restrict__ W_edge,
    const float* __restrict__ w_out,
    float* __restrict__ out,
    int L)
{
    __shared__ int   sJI[LMAX];                 // j | (it<<16)
    __shared__ float sPj[LMAX];
    __shared__ float sDx[LMAX], sDy[LMAX], sDz[LMAX];
    __shared__ int   wsum[8];
    __shared__ float sred[8][3];

    const int tid  = threadIdx.x;
    const int lane = tid & 31;
    const int wrp  = tid >> 5;
    const int sub  = lane & 7;    // m-slice within edge group
    const int es   = lane >> 3;   // edge slot (0..3)

    // per-lane weight slices (registers): only w1 (pij row) and w_out
    const int mb = sub * 8;
    float w1r[8], wor[8];
    {
        float4 c = *(const float4*)(W_edge + MM + mb);
        float4 d = *(const float4*)(W_edge + MM + mb + 4);
        float4 e = *(const float4*)(w_out + mb);
        float4 f = *(const float4*)(w_out + mb + 4);
        w1r[0]=c.x; w1r[1]=c.y; w1r[2]=c.z; w1r[3]=c.w;
        w1r[4]=d.x; w1r[5]=d.y; w1r[6]=d.z; w1r[7]=d.w;
        wor[0]=e.x; wor[1]=e.y; wor[2]=e.z; wor[3]=e.w;
        wor[4]=f.x; wor[5]=f.y; wor[6]=f.z; wor[7]=f.w;
    }

    for (int half = 0; half < 2; half++) {
        const int i = half ? (L - 1 - (int)blockIdx.x) : (int)blockIdx.x;
        __syncthreads();   // smem reuse across halves

        const float xi = xyz[i * 3 + 0];
        const float yi = xyz[i * 3 + 1];
        const float zi = xyz[i * 3 + 2];

        // ---- compaction: CONTACT edges only (j > i+2, P > 0.2) ----
        const float4 p4 = reinterpret_cast<const float4*>(P + (size_t)i * L)[tid];
        float pv[4] = {p4.x, p4.y, p4.z, p4.w};
        int myj[4]; float myp[4]; int c = 0;
        const int jb = tid * 4;
        #pragma unroll
        for (int r = 0; r < 4; r++) {
            int j = jb + r;
            if ((pv[r] > 0.2f) && (j > i + 2)) { myj[c] = j; myp[c] = pv[r]; c++; }
        }
        int inc = c;
        #pragma unroll
        for (int off = 1; off < 32; off <<= 1) {
            int v = __shfl_up_sync(0xffffffffu, inc, off);
            if (lane >= off) inc += v;
        }
        if (lane == 31) wsum[wrp] = inc;
        __syncthreads();
        int offset = inc - c;
        int total  = 0;
        #pragma unroll
        for (int q = 0; q < 8; q++) {
            int wv = wsum[q];
            if (q < wrp) offset += wv;
            total += wv;
        }
        for (int t = 0; t < c; t++) { sJI[offset + t] = myj[t]; sPj[offset + t] = myp[t]; }
        __syncthreads();

        const int padded = (total + 63) & ~63;

        // ---- per-edge geometry + packed (j, table index) ----
        for (int e = tid; e < padded; e += 256) {
            if (e < total) {
                int j = sJI[e];
                float dx = xyz[3 * j + 0] - xi;
                float dy = xyz[3 * j + 1] - yi;
                float dz = xyz[3 * j + 2] - zi;
                float d  = sqrtf(fmaf(dx, dx, fmaf(dy, dy, fmaf(dz, dz, 1e-12f))));
                int it = (int)(d * TSCALE + 0.5f);
                it = (it > NT - 1) ? (NT - 1) : it;
                sJI[e] = j | (it << 16);
                sDx[e] = dx; sDy[e] = dy; sDz[e] = dz;
            } else {
                sJI[e] = 0; sPj[e] = 0.f;
                sDx[e] = 0.f; sDy[e] = 0.f; sDz[e] = 0.f;
            }
        }
        __syncthreads();

        // ---- main loop: 8 edges per warp-iteration ----
        float ax = 0.f, ay = 0.f, az = 0.f;
        for (int eb = wrp * 8; eb < padded; eb += 64) {
            const int e1 = eb + es;
            const int e2 = eb + 4 + es;
            const int ji1 = sJI[e1], ji2 = sJI[e2];
            const float p1 = sPj[e1], p2 = sPj[e2];
            const int j1 = ji1 & 0xFFFF, it1 = ji1 >> 16;
            const int j2 = ji2 & 0xFFFF, it2 = ji2 >> 16;

            uint4 nb1 = *reinterpret_cast<const uint4*>(g_nb16 + j1 * MM + mb);
            uint4 tv1 = *reinterpret_cast<const uint4*>(g_T16 + (size_t)it1 * MM + mb);
            uint4 nb2 = *reinterpret_cast<const uint4*>(g_nb16 + j2 * MM + mb);
            uint4 tv2 = *reinterpret_cast<const uint4*>(g_T16 + (size_t)it2 * MM + mb);

            const __half2* nh1 = reinterpret_cast<const __half2*>(&nb1);
            const __half2* th1 = reinterpret_cast<const __half2*>(&tv1);
            const __half2* nh2 = reinterpret_cast<const __half2*>(&nb2);
            const __half2* th2 = reinterpret_cast<const __half2*>(&tv2);

            float g1 = 0.f, g2 = 0.f;
            #pragma unroll
            for (int q = 0; q < 4; q++) {
                float2 f1 = __half22float2(__hadd2(nh1[q], th1[q]));
                float2 f2 = __half22float2(__hadd2(nh2[q], th2[q]));
                float w1a = w1r[2 * q], w1b = w1r[2 * q + 1];
                float woa = wor[2 * q], wob = wor[2 * q + 1];

                float a0 = fmaf(p1, w1a, f1.x);
                float a1 = fmaf(p1, w1b, f1.y);
                g1 = fmaf(fmaxf(a0, 0.f), woa, g1);
                g1 = fmaf(fmaxf(a1, 0.f), wob, g1);

                float b0 = fmaf(p2, w1a, f2.x);
                float b1 = fmaf(p2, w1b, f2.y);
                g2 = fmaf(fmaxf(b0, 0.f), woa, g2);
                g2 = fmaf(fmaxf(b1, 0.f), wob, g2);
            }
            g1 += __shfl_xor_sync(0xffffffffu, g1, 1);
            g2 += __shfl_xor_sync(0xffffffffu, g2, 1);
            g1 += __shfl_xor_sync(0xffffffffu, g1, 2);
            g2 += __shfl_xor_sync(0xffffffffu, g2, 2);
            g1 += __shfl_xor_sync(0xffffffffu, g1, 4);
            g2 += __shfl_xor_sync(0xffffffffu, g2, 4);

            if (sub == 0) {
                if (e1 < total) {
                    float gate = __fdividef(1.f, 1.f + __expf(-g1));
                    ax = fmaf(gate, sDx[e1], ax);
                    ay = fmaf(gate, sDy[e1], ay);
                    az = fmaf(gate, sDz[e1], az);
                }
                if (e2 < total) {
                    float gate = __fdividef(1.f, 1.f + __expf(-g2));
                    ax = fmaf(gate, sDx[e2], ax);
                    ay = fmaf(gate, sDy[e2], ay);
                    az = fmaf(gate, sDz[e2], az);
                }
            }
        }

        // ---- backbone edge (j = i+1): warp 0, 2 m per lane ----
        if (wrp == 0 && i + 1 < L) {
            const int j = i + 1;
            const float dx = xyz[3 * j + 0] - xi;
            const float dy = xyz[3 * j + 1] - yi;
            const float dz = xyz[3 * j + 2] - zi;
            const float d  = sqrtf(fmaf(dx, dx, fmaf(dy, dy, fmaf(dz, dz, 1e-12f))));
            int it = (int)(d * TSCALE + 0.5f);
            it = (it > NT - 1) ? (NT - 1) : it;

            const int m2 = lane * 2;
            __half2 nb = *reinterpret_cast<const __half2*>(g_nb16 + j * MM + m2);
            __half2 tv = *reinterpret_cast<const __half2*>(g_T16 + (size_t)it * MM + m2);
            float2 f  = __half22float2(__hadd2(nb, tv));
            float2 w0 = *reinterpret_cast<const float2*>(W_edge + m2);
            float2 w1 = *reinterpret_cast<const float2*>(W_edge + MM + m2);
            float2 wo = *reinterpret_cast<const float2*>(w_out + m2);
            // msg = nb + T + w1 = nb + T' - w0 + w1  (et=0, pij=1)
            float a0 = f.x - w0.x + w1.x;
            float a1 = f.y - w0.y + w1.y;
            float gb = fmaf(fmaxf(a0, 0.f), wo.x, fmaxf(a1, 0.f) * wo.y);
            #pragma unroll
            for (int off = 16; off; off >>= 1)
                gb += __shfl_down_sync(0xffffffffu, gb, off);
            if (lane == 0) {
                float gate = __fdividef(1.f, 1.f + __expf(-gb));
                ax = fmaf(gate, dx, ax);
                ay = fmaf(gate, dy, ay);
                az = fmaf(gate, dz, az);
            }
        }

        // ---- deterministic block reduction ----
        #pragma unroll
        for (int off = 16; off; off >>= 1) {
            ax += __shfl_down_sync(0xffffffffu, ax, off);
            ay += __shfl_down_sync(0xffffffffu, ay, off);
            az += __shfl_down_sync(0xffffffffu, az, off);
        }
        if (lane == 0) { sred[wrp][0] = ax; sred[wrp][1] = ay; sred[wrp][2] = az; }
        __syncthreads();
        if (tid == 0) {
            float tx = 0.f, ty = 0.f, tz = 0.f;
            #pragma unroll
            for (int q = 0; q < 8; q++) { tx += sred[q][0]; ty += sred[q][1]; tz += sred[q][2]; }
            out[i * 3 + 0] = xi + tx;
            out[i * 3 + 1] = yi + ty;
            out[i * 3 + 2] = zi + tz;
        }
    }
}

// ---------------------------------------------------------------------------
extern "C" void kernel_launch(void* const* d_in, const int* in_sizes, int n_in,
                              void* d_out, int out_size)
{
    const float* S         = (const float*)d_in[0];
    const float* P         = (const float*)d_in[1];
    const float* xyz       = (const float*)d_in[2];
    const float* rbf_mu    = (const float*)d_in[3];
    const float* rbf_sigma = (const float*)d_in[4];
    const float* W_edge    = (const float*)d_in[5];
    const float* b_edge    = (const float*)d_in[6];
    const float* W_node    = (const float*)d_in[7];
    const float* w_out     = (const float*)d_in[8];
    float* out = (float*)d_out;

    int L = in_sizes[2] / 3;          // 1024
    int D = in_sizes[0] / L;          // 640

    prep_kernel<<<128 + NT / 32, 256>>>(S, W_node, b_edge,
                                        rbf_mu, rbf_sigma, W_edge, L, D);
    edge_kernel<<<L / 2, 256>>>(P, xyz, W_edge, w_out, out, L);
}

// round 9
// speedup vs baseline: 26.3263x; 1.4189x over previous
#include <cuda_runtime.h>
#include <cuda_fp16.h>

// Shapes fixed by the problem: L=1024, D=640, K=32, M=64
#define LMAX 1024
#define MM   64
#define NT   4096          // RBF table rows, d in [0, 64), h = 1/64
#define TSCALE 64.0f

// fp16 scratch (L1/L2-resident)
__device__ __half g_nb16[LMAX * MM];   // 128 KB  (node proj + bias)
__device__ __half g_T16[NT * MM];      // 512 KB  (w0 + RBF @ W_edge[2:34])

// ---------------------------------------------------------------------------
// Fused prep kernel:
//   blocks [0,128)   : node projection, 8 rows each
//   blocks [128,256) : RBF table, 32 t-rows each (w0 baked in)
// ---------------------------------------------------------------------------
__global__ void __launch_bounds__(256) prep_kernel(
    const float* __restrict__ S,
    const float* __restrict__ W_node,
    const float* __restrict__ b_edge,
    const float* __restrict__ rbf_mu,
    const float* __restrict__ rbf_sigma,
    const float* __restrict__ W_edge,
    int L, int D)
{
    __shared__ __align__(16) float sbuf[4672];
    const int tid = threadIdx.x;

    if (blockIdx.x < 128) {
        // ---------------- node projection ----------------
        float (*sS)[64] = reinterpret_cast<float (*)[64]>(sbuf);          // 8 x 64
        float (*sW)[65] = reinterpret_cast<float (*)[65]>(sbuf + 512);    // 64 x 65

        const int m  = tid & 63;
        const int jr = tid >> 6;
        const int j0 = blockIdx.x * 8;

        float a0 = 0.f, a1 = 0.f;
        float wreg[16], s0, s1;

        s0 = S[(size_t)(j0 + jr) * D + m];
        s1 = S[(size_t)(j0 + jr + 4) * D + m];
        #pragma unroll
        for (int r = 0; r < 16; r++)
            wreg[r] = W_node[(size_t)(r * 4 + jr) * MM + m];

        for (int d0 = 0; d0 < D; d0 += 64) {
            sS[jr][m]     = s0;
            sS[jr + 4][m] = s1;
            #pragma unroll
            for (int r = 0; r < 16; r++)
                sW[r * 4 + jr][m] = wreg[r];
            __syncthreads();
            int dn = d0 + 64;
            if (dn < D) {
                s0 = S[(size_t)(j0 + jr) * D + dn + m];
                s1 = S[(size_t)(j0 + jr + 4) * D + dn + m];
                #pragma unroll
                for (int r = 0; r < 16; r++)
                    wreg[r] = W_node[(size_t)(dn + r * 4 + jr) * MM + m];
            }
            #pragma unroll
            for (int d = 0; d < 64; d++) {
                float w = sW[d][m];
                a0 = fmaf(sS[jr][d], w, a0);
                a1 = fmaf(sS[jr + 4][d], w, a1);
            }
            __syncthreads();
        }
        float b = b_edge[m];
        g_nb16[(j0 + jr) * MM + m]     = __float2half_rn(a0 + b);
        g_nb16[(j0 + jr + 4) * MM + m] = __float2half_rn(a1 + b);
    } else {
        // ---------------- RBF table (+w0 baked) ----------------
        float* se = sbuf;                       // 32 rows x 32 k
        const int t0   = (blockIdx.x - 128) * 32;
        const int m    = tid & 63;
        const int slot = tid >> 6;              // 0..3 -> rows slot*8..slot*8+7

        for (int v = tid; v < 32 * 32; v += 256) {
            int t = v >> 5, k = v & 31;
            float g  = (float)(t0 + t) * (1.0f / TSCALE);
            float mu = rbf_mu[k];
            float s  = rbf_sigma[k];
            float dd = g - mu;
            se[v] = __expf(-dd * dd / (2.0f * s * s));
        }
        float wreg[32];
        #pragma unroll
        for (int k = 0; k < 32; k++)
            wreg[k] = W_edge[(k + 2) * MM + m];
        const float w0 = W_edge[m];
        __syncthreads();

        float acc[8];
        #pragma unroll
        for (int r = 0; r < 8; r++) acc[r] = w0;
        #pragma unroll
        for (int k = 0; k < 32; k++) {
            float w = wreg[k];
            #pragma unroll
            for (int r = 0; r < 8; r++)
                acc[r] = fmaf(se[(slot * 8 + r) * 32 + k], w, acc[r]);
        }
        #pragma unroll
        for (int r = 0; r < 8; r++)
            g_T16[(size_t)(t0 + slot * 8 + r) * MM + m] = __float2half_rn(acc[r]);
    }
}

// ---------------------------------------------------------------------------
// Kernel 2: grid 512, block 256; block b does rows b and 1023-b.
// Contacts only (w0 baked into T'): full half2 inner loop
//   msg2 = hmax2(hfma2(pij, w1, nb+T'), 0);  g2 = hfma2(msg2, wo, g2)
// 8 lanes per edge, 8 edges per warp-iteration. Backbone handled by warp 0.
// ---------------------------------------------------------------------------
__global__ void __launch_bounds__(256, 4) edge_kernel(
    const float* __restrict__ P,
    const float* __restrict__ xyz,
    const float* __restrict__ W_edge,
    const float* __restrict__ w_out,
    float* __restrict__ out,
    int L)
{
    __shared__ int    sJI[LMAX];                 // j | (it<<16)
    __shared__ __half sPh[LMAX];
    __shared__ float  sDx[LMAX], sDy[LMAX], sDz[LMAX];
    __shared__ int    wsum[8];
    __shared__ float  sred[8][3];

    const int tid  = threadIdx.x;
    const int lane = tid & 31;
    const int wrp  = tid >> 5;
    const int sub  = lane & 7;    // m-slice within edge group
    const int es   = lane >> 3;   // edge slot (0..3)

    // per-lane weight slices as half2 (w1 = pij row, wo = out weights)
    const int mb = sub * 8;
    __half2 w1h[4], woh[4];
    {
        float4 c = *(const float4*)(W_edge + MM + mb);
        float4 d = *(const float4*)(W_edge + MM + mb + 4);
        float4 e = *(const float4*)(w_out + mb);
        float4 f = *(const float4*)(w_out + mb + 4);
        w1h[0] = __floats2half2_rn(c.x, c.y);
        w1h[1] = __floats2half2_rn(c.z, c.w);
        w1h[2] = __floats2half2_rn(d.x, d.y);
        w1h[3] = __floats2half2_rn(d.z, d.w);
        woh[0] = __floats2half2_rn(e.x, e.y);
        woh[1] = __floats2half2_rn(e.z, e.w);
        woh[2] = __floats2half2_rn(f.x, f.y);
        woh[3] = __floats2half2_rn(f.z, f.w);
    }
    const __half2 hz = __float2half2_rn(0.f);

    for (int half = 0; half < 2; half++) {
        const int i = half ? (L - 1 - (int)blockIdx.x) : (int)blockIdx.x;
        __syncthreads();   // smem reuse across halves

        const float xi = xyz[i * 3 + 0];
        const float yi = xyz[i * 3 + 1];
        const float zi = xyz[i * 3 + 2];

        // ---- compaction: CONTACT edges only (j > i+2, P > 0.2) ----
        const float4 p4 = reinterpret_cast<const float4*>(P + (size_t)i * L)[tid];
        float pv[4] = {p4.x, p4.y, p4.z, p4.w};
        int myj[4]; float myp[4]; int c = 0;
        const int jb = tid * 4;
        #pragma unroll
        for (int r = 0; r < 4; r++) {
            int j = jb + r;
            if ((pv[r] > 0.2f) && (j > i + 2)) { myj[c] = j; myp[c] = pv[r]; c++; }
        }
        int inc = c;
        #pragma unroll
        for (int off = 1; off < 32; off <<= 1) {
            int v = __shfl_up_sync(0xffffffffu, inc, off);
            if (lane >= off) inc += v;
        }
        if (lane == 31) wsum[wrp] = inc;
        __syncthreads();
        int offset = inc - c;
        int total  = 0;
        #pragma unroll
        for (int q = 0; q < 8; q++) {
            int wv = wsum[q];
            if (q < wrp) offset += wv;
            total += wv;
        }
        for (int t = 0; t < c; t++) {
            sJI[offset + t] = myj[t];
            sPh[offset + t] = __float2half_rn(myp[t]);
        }
        __syncthreads();

        const int padded = (total + 63) & ~63;

        // ---- per-edge geometry + packed (j, table index) ----
        for (int e = tid; e < padded; e += 256) {
            if (e < total) {
                int j = sJI[e];
                float dx = xyz[3 * j + 0] - xi;
                float dy = xyz[3 * j + 1] - yi;
                float dz = xyz[3 * j + 2] - zi;
                float d  = sqrtf(fmaf(dx, dx, fmaf(dy, dy, fmaf(dz, dz, 1e-12f))));
                int it = (int)(d * TSCALE + 0.5f);
                it = (it > NT - 1) ? (NT - 1) : it;
                sJI[e] = j | (it << 16);
                sDx[e] = dx; sDy[e] = dy; sDz[e] = dz;
            } else {
                sJI[e] = 0; sPh[e] = __float2half_rn(0.f);
                sDx[e] = 0.f; sDy[e] = 0.f; sDz[e] = 0.f;
            }
        }
        __syncthreads();

        // ---- main loop: 8 edges per warp-iteration, full half2 math ----
        float ax = 0.f, ay = 0.f, az = 0.f;
        for (int eb = wrp * 8; eb < padded; eb += 64) {
            const int e1 = eb + es;
            const int e2 = eb + 4 + es;
            const int ji1 = sJI[e1], ji2 = sJI[e2];
            const __half2 p1h = __half2half2(sPh[e1]);
            const __half2 p2h = __half2half2(sPh[e2]);
            const int j1 = ji1 & 0xFFFF, it1 = ji1 >> 16;
            const int j2 = ji2 & 0xFFFF, it2 = ji2 >> 16;

            uint4 nb1 = *reinterpret_cast<const uint4*>(g_nb16 + j1 * MM + mb);
            uint4 tv1 = *reinterpret_cast<const uint4*>(g_T16 + (size_t)it1 * MM + mb);
            uint4 nb2 = *reinterpret_cast<const uint4*>(g_nb16 + j2 * MM + mb);
            uint4 tv2 = *reinterpret_cast<const uint4*>(g_T16 + (size_t)it2 * MM + mb);

            const __half2* nh1 = reinterpret_cast<const __half2*>(&nb1);
            const __half2* th1 = reinterpret_cast<const __half2*>(&tv1);
            const __half2* nh2 = reinterpret_cast<const __half2*>(&nb2);
            const __half2* th2 = reinterpret_cast<const __half2*>(&tv2);

            __half2 g1h = hz, g2h = hz;
            #pragma unroll
            for (int q = 0; q < 4; q++) {
                __half2 m1 = __hfma2(p1h, w1h[q], __hadd2(nh1[q], th1[q]));
                __half2 m2 = __hfma2(p2h, w1h[q], __hadd2(nh2[q], th2[q]));
                m1 = __hmax2(m1, hz);
                m2 = __hmax2(m2, hz);
                g1h = __hfma2(m1, woh[q], g1h);
                g2h = __hfma2(m2, woh[q], g2h);
            }
            float2 gf1 = __half22float2(g1h);
            float2 gf2 = __half22float2(g2h);
            float g1 = gf1.x + gf1.y;
            float g2 = gf2.x + gf2.y;

            g1 += __shfl_xor_sync(0xffffffffu, g1, 1);
            g2 += __shfl_xor_sync(0xffffffffu, g2, 1);
            g1 += __shfl_xor_sync(0xffffffffu, g1, 2);
            g2 += __shfl_xor_sync(0xffffffffu, g2, 2);
            g1 += __shfl_xor_sync(0xffffffffu, g1, 4);
            g2 += __shfl_xor_sync(0xffffffffu, g2, 4);

            if (sub == 0) {
                if (e1 < total) {
                    float gate = __fdividef(1.f, 1.f + __expf(-g1));
                    ax = fmaf(gate, sDx[e1], ax);
                    ay = fmaf(gate, sDy[e1], ay);
                    az = fmaf(gate, sDz[e1], az);
                }
                if (e2 < total) {
                    float gate = __fdividef(1.f, 1.f + __expf(-g2));
                    ax = fmaf(gate, sDx[e2], ax);
                    ay = fmaf(gate, sDy[e2], ay);
                    az = fmaf(gate, sDz[e2], az);
                }
            }
        }

        // ---- backbone edge (j = i+1): warp 0, float math, 2 m per lane ----
        if (wrp == 0 && i + 1 < L) {
            const int j = i + 1;
            const float dx = xyz[3 * j + 0] - xi;
            const float dy = xyz[3 * j + 1] - yi;
            const float dz = xyz[3 * j + 2] - zi;
            const float d  = sqrtf(fmaf(dx, dx, fmaf(dy, dy, fmaf(dz, dz, 1e-12f))));
            int it = (int)(d * TSCALE + 0.5f);
            it = (it > NT - 1) ? (NT - 1) : it;

            const int m2 = lane * 2;
            __half2 nb = *reinterpret_cast<const __half2*>(g_nb16 + j * MM + m2);
            __half2 tv = *reinterpret_cast<const __half2*>(g_T16 + (size_t)it * MM + m2);
            float2 f  = __half22float2(__hadd2(nb, tv));
            float2 w0 = *reinterpret_cast<const float2*>(W_edge + m2);
            float2 w1 = *reinterpret_cast<const float2*>(W_edge + MM + m2);
            float2 wo = *reinterpret_cast<const float2*>(w_out + m2);
            // msg = nb + T + w1 = nb + T' - w0 + w1  (et=0, pij=1)
            float a0 = f.x - w0.x + w1.x;
            float a1 = f.y - w0.y + w1.y;
            float gb = fmaf(fmaxf(a0, 0.f), wo.x, fmaxf(a1, 0.f) * wo.y);
            #pragma unroll
            for (int off = 16; off; off >>= 1)
                gb += __shfl_down_sync(0xffffffffu, gb, off);
            if (lane == 0) {
                float gate = __fdividef(1.f, 1.f + __expf(-gb));
                ax = fmaf(gate, dx, ax);
                ay = fmaf(gate, dy, ay);
                az = fmaf(gate, dz, az);
            }
        }

        // ---- deterministic block reduction ----
        #pragma unroll
        for (int off = 16; off; off >>= 1) {
            ax += __shfl_down_sync(0xffffffffu, ax, off);
            ay += __shfl_down_sync(0xffffffffu, ay, off);
            az += __shfl_down_sync(0xffffffffu, az, off);
        }
        if (lane == 0) { sred[wrp][0] = ax; sred[wrp][1] = ay; sred[wrp][2] = az; }
        __syncthreads();
        if (tid == 0) {
            float tx = 0.f, ty = 0.f, tz = 0.f;
            #pragma unroll
            for (int q = 0; q < 8; q++) { tx += sred[q][0]; ty += sred[q][1]; tz += sred[q][2]; }
            out[i * 3 + 0] = xi + tx;
            out[i * 3 + 1] = yi + ty;
            out[i * 3 + 2] = zi + tz;
        }
    }
}

// ---------------------------------------------------------------------------
extern "C" void kernel_launch(void* const* d_in, const int* in_sizes, int n_in,
                              void* d_out, int out_size)
{
    const float* S         = (const float*)d_in[0];
    const float* P         = (const float*)d_in[1];
    const float* xyz       = (const float*)d_in[2];
    const float* rbf_mu    = (const float*)d_in[3];
    const float* rbf_sigma = (const float*)d_in[4];
    const float* W_edge    = (const float*)d_in[5];
    const float* b_edge    = (const float*)d_in[6];
    const float* W_node    = (const float*)d_in[7];
    const float* w_out     = (const float*)d_in[8];
    float* out = (float*)d_out;

    int L = in_sizes[2] / 3;          // 1024
    int D = in_sizes[0] / L;          // 640

    prep_kernel<<<128 + NT / 32, 256>>>(S, W_node, b_edge,
                                        rbf_mu, rbf_sigma, W_edge, L, D);
    edge_kernel<<<L / 2, 256>>>(P, xyz, W_edge, w_out, out, L);
}